// round 16
// baseline (speedup 1.0000x reference)
#include <cuda_runtime.h>
#include <cuda_fp16.h>
#include <math.h>
#include <stdint.h>

#define VOCAB 50257
#define DHID  128
#define NTOK  1024
#define NFREQ 256
#define SEQ   512

// ---------------- device scratch ----------------
__device__ __align__(16) float g_xr[NTOK*DHID];
__device__ __align__(16) float g_xi[NTOK*DHID];
__device__ __align__(16) float g_xc[NTOK*DHID];
__device__ __align__(16) float g_cs[NTOK*NFREQ];
__device__ __align__(16) float g_ss[NTOK*NFREQ];
__device__ __align__(16) __half g_Wr16[VOCAB*DHID];
__device__ __align__(16) __half g_Wi16[VOCAB*DHID];
__device__ __align__(16) __half g_Ar16[NTOK*DHID];
__device__ __align__(16) __half g_Ai16[NTOK*DHID];
__device__ __align__(16) __half g_opr16[DHID*NFREQ];   // layer-1 op weights only
__device__ __align__(16) __half g_opi16[DHID*NFREQ];

// ---------------- small kernels ----------------
__global__ void wsplit_kernel(const float* __restrict__ Wr, const float* __restrict__ Wi) {
    int i = blockIdx.x*256 + threadIdx.x;
    if (i < VOCAB*DHID) {
        g_Wr16[i] = __float2half(Wr[i]);
        g_Wi16[i] = __float2half(Wi[i]);
    }
}

__global__ void opsplit_kernel(const float* __restrict__ opr1, const float* __restrict__ opi1) {
    int i = blockIdx.x*256 + threadIdx.x;   // 128*256 = 32768 elements (layer 1)
    g_opr16[i] = __float2half(opr1[i]);
    g_opi16[i] = __float2half(opi1[i]);
}

// xc[t][d] = sum_k in[t][k] * cw[d][k] + cb[d]   (K=256, fp32 weights — LUT-sensitive)
// 8 tokens/block, 512 threads, split-K x4, grid 128 (proven R13 config).
__global__ void __launch_bounds__(512, 2)
xc_kernel(const float* __restrict__ cwl, const float* __restrict__ cbl,
          const int* __restrict__ ids, const float* __restrict__ emb,
          int gather) {
    __shared__ __align__(16) float sbuf[4096];   // inputs 8KB -> partials 16KB
    float* xs = sbuf;                            // [8][256]
    int tid = threadIdx.x, tBase = blockIdx.x*8;
    if (gather) {
        for (int i = tid; i < 8*256; i += 512) {
            int t = i >> 8, k = i & 255;
            xs[i] = emb[(size_t)ids[tBase+t]*256 + k];
        }
    } else {
        for (int i = tid; i < 8*256; i += 512) {
            int t = i >> 8, k = i & 255;
            xs[i] = (k < 128) ? g_xr[(tBase+t)*DHID + k] : g_xi[(tBase+t)*DHID + k - 128];
        }
    }
    __syncthreads();
    const int d = tid & 127, kq = tid >> 7;
    const int k0 = kq*64;
    float acc[8];
    #pragma unroll
    for (int t = 0; t < 8; t++) acc[t] = 0.f;
    #pragma unroll 4
    for (int k = k0; k < k0 + 64; k += 4) {
        float4 w = *reinterpret_cast<const float4*>(&cwl[d*256 + k]);
        #pragma unroll
        for (int t = 0; t < 8; t++) {
            acc[t] = fmaf(w.x, xs[t*256+k+0], acc[t]);
            acc[t] = fmaf(w.y, xs[t*256+k+1], acc[t]);
            acc[t] = fmaf(w.z, xs[t*256+k+2], acc[t]);
            acc[t] = fmaf(w.w, xs[t*256+k+3], acc[t]);
        }
    }
    __syncthreads();
    #pragma unroll
    for (int t = 0; t < 8; t++) sbuf[t*512 + kq*128 + d] = acc[t];
    __syncthreads();
    #pragma unroll
    for (int j = 0; j < 2; j++) {
        int o = tid + j*512;
        int t = o >> 7, dd = o & 127;
        float v = (sbuf[t*512 + dd] + sbuf[t*512 + 128 + dd])
                + (sbuf[t*512 + 256 + dd] + sbuf[t*512 + 384 + dd]);
        g_xc[(tBase+t)*DHID + dd] = v + cbl[dd];
    }
}

// lane = token, warp = frequency: serial d-accumulation, no shuffles.
__global__ void theta_kernel(const float* __restrict__ Wl, const float* __restrict__ Bpl,
                             const float* __restrict__ acl, const float* __restrict__ asl) {
    __shared__ __align__(16) float  xs[32*129];
    __shared__ __align__(16) float4 wt[4*128];
    const float KSCALE = (float)(4096.0 / 6.283185307179586);
    const float ASTEP  = (float)(6.283185307179586 / 4096.0);
    const float PHI_F  = 1.6180339887498948f;
    const int tid = threadIdx.x, warp = tid >> 5, lane = tid & 31;
    const int nBase = blockIdx.x*4;
    const int tBase = blockIdx.y*32;

    for (int i = tid; i < 32*128; i += 128) {
        int t = i >> 7, d = i & 127;
        xs[t*129 + d] = g_xc[(tBase+t)*DHID + d];
    }
    for (int i = tid; i < 4*128; i += 128) {
        int n = nBase + (i >> 7), d = i & 127;
        float w = Wl[n*DHID + d];
        wt[i] = make_float4(1.0f/(1.0f + fabsf(w)), Bpl[n*DHID + d],
                            acl[n*DHID + d], asl[n*DHID + d]);
    }
    __syncthreads();

    const int n = nBase + warp;
    const int tok = tBase + lane;
    const float tpos = (float)(tok & (SEQ-1)) * PHI_F;
    const float4* wrow = wt + warp*128;
    const float*  xrow = xs + lane*129;
    float cs = 0.f, ss = 0.f;
    #pragma unroll 4
    for (int d = 0; d < 128; d++) {
        float4 c = wrow[d];
        float th = fmaf(xrow[d], c.x, c.y) + tpos;
        int idx = __float2int_rd(th * KSCALE) & 4095;
        float sv, cv;
        __sincosf((float)idx * ASTEP, &sv, &cv);
        cs = fmaf(cv, c.z, cs);
        ss = fmaf(sv, c.w, ss);
    }
    g_cs[tok*NFREQ + n] = cs;
    g_ss[tok*NFREQ + n] = ss;
}

// Layer 0: xr/xi = silu(cs @ opr^T), silu(ss @ opi^T)  — fp32 weights (bit-exact R13 path)
__global__ void __launch_bounds__(512, 2)
op_kernel(const float* __restrict__ oprl, const float* __restrict__ opil) {
    __shared__ __align__(16) float sbuf[8192];
    float* cs_s = sbuf;          // [8][256]
    float* ss_s = sbuf + 2048;   // [8][256]
    int tid = threadIdx.x, tBase = blockIdx.x*8;
    for (int i = tid; i < 8*256; i += 512) {
        int t = i >> 8, k = i & 255;
        cs_s[i] = g_cs[(tBase+t)*NFREQ + k];
        ss_s[i] = g_ss[(tBase+t)*NFREQ + k];
    }
    __syncthreads();
    const int d = tid & 127, kq = tid >> 7;
    const int k0 = kq*64;
    float accr[8], acci[8];
    #pragma unroll
    for (int t = 0; t < 8; t++) { accr[t] = 0.f; acci[t] = 0.f; }
    #pragma unroll 2
    for (int k = k0; k < k0 + 64; k += 4) {
        float4 wr = *reinterpret_cast<const float4*>(&oprl[d*256 + k]);
        float4 wi = *reinterpret_cast<const float4*>(&opil[d*256 + k]);
        #pragma unroll
        for (int t = 0; t < 8; t++) {
            accr[t] = fmaf(wr.x, cs_s[t*256+k+0], accr[t]);
            accr[t] = fmaf(wr.y, cs_s[t*256+k+1], accr[t]);
            accr[t] = fmaf(wr.z, cs_s[t*256+k+2], accr[t]);
            accr[t] = fmaf(wr.w, cs_s[t*256+k+3], accr[t]);
            acci[t] = fmaf(wi.x, ss_s[t*256+k+0], acci[t]);
            acci[t] = fmaf(wi.y, ss_s[t*256+k+1], acci[t]);
            acci[t] = fmaf(wi.z, ss_s[t*256+k+2], acci[t]);
            acci[t] = fmaf(wi.w, ss_s[t*256+k+3], acci[t]);
        }
    }
    __syncthreads();
    #pragma unroll
    for (int t = 0; t < 8; t++) {
        sbuf[t*512 + kq*128 + d]        = accr[t];
        sbuf[4096 + t*512 + kq*128 + d] = acci[t];
    }
    __syncthreads();
    #pragma unroll
    for (int j = 0; j < 2; j++) {
        int o = tid + j*512;
        int t = o >> 7, dd = o & 127;
        float vr = (sbuf[t*512 + dd] + sbuf[t*512 + 128 + dd])
                 + (sbuf[t*512 + 256 + dd] + sbuf[t*512 + 384 + dd]);
        float vi = (sbuf[4096 + t*512 + dd] + sbuf[4096 + t*512 + 128 + dd])
                 + (sbuf[4096 + t*512 + 256 + dd] + sbuf[4096 + t*512 + 384 + dd]);
        g_xr[(tBase+t)*DHID + dd] = vr / (1.0f + expf(-vr));
        g_xi[(tBase+t)*DHID + dd] = vi / (1.0f + expf(-vi));
    }
}

// Layer 1: same GEMM but fp16 weights (output only feeds the fp16 final GEMM);
// writes fp16 A operands directly.
__global__ void __launch_bounds__(512, 2)
op16_kernel() {
    __shared__ __align__(16) float sbuf[8192];
    float* cs_s = sbuf;          // [8][256]
    float* ss_s = sbuf + 2048;   // [8][256]
    int tid = threadIdx.x, tBase = blockIdx.x*8;
    for (int i = tid; i < 8*256; i += 512) {
        int t = i >> 8, k = i & 255;
        cs_s[i] = g_cs[(tBase+t)*NFREQ + k];
        ss_s[i] = g_ss[(tBase+t)*NFREQ + k];
    }
    __syncthreads();
    const int d = tid & 127, kq = tid >> 7;
    const int k0 = kq*64;
    const __half* wr16 = g_opr16 + d*256;
    const __half* wi16 = g_opi16 + d*256;
    float accr[8], acci[8];
    #pragma unroll
    for (int t = 0; t < 8; t++) { accr[t] = 0.f; acci[t] = 0.f; }
    #pragma unroll 2
    for (int k = k0; k < k0 + 64; k += 8) {
        uint4 rv = *reinterpret_cast<const uint4*>(wr16 + k);
        uint4 iv = *reinterpret_cast<const uint4*>(wi16 + k);
        float2 r01 = __half22float2(*reinterpret_cast<__half2*>(&rv.x));
        float2 r23 = __half22float2(*reinterpret_cast<__half2*>(&rv.y));
        float2 r45 = __half22float2(*reinterpret_cast<__half2*>(&rv.z));
        float2 r67 = __half22float2(*reinterpret_cast<__half2*>(&rv.w));
        float2 i01 = __half22float2(*reinterpret_cast<__half2*>(&iv.x));
        float2 i23 = __half22float2(*reinterpret_cast<__half2*>(&iv.y));
        float2 i45 = __half22float2(*reinterpret_cast<__half2*>(&iv.z));
        float2 i67 = __half22float2(*reinterpret_cast<__half2*>(&iv.w));
        #pragma unroll
        for (int t = 0; t < 8; t++) {
            const float* cr = cs_s + t*256 + k;
            const float* si = ss_s + t*256 + k;
            accr[t] = fmaf(r01.x, cr[0], accr[t]);
            accr[t] = fmaf(r01.y, cr[1], accr[t]);
            accr[t] = fmaf(r23.x, cr[2], accr[t]);
            accr[t] = fmaf(r23.y, cr[3], accr[t]);
            accr[t] = fmaf(r45.x, cr[4], accr[t]);
            accr[t] = fmaf(r45.y, cr[5], accr[t]);
            accr[t] = fmaf(r67.x, cr[6], accr[t]);
            accr[t] = fmaf(r67.y, cr[7], accr[t]);
            acci[t] = fmaf(i01.x, si[0], acci[t]);
            acci[t] = fmaf(i01.y, si[1], acci[t]);
            acci[t] = fmaf(i23.x, si[2], acci[t]);
            acci[t] = fmaf(i23.y, si[3], acci[t]);
            acci[t] = fmaf(i45.x, si[4], acci[t]);
            acci[t] = fmaf(i45.y, si[5], acci[t]);
            acci[t] = fmaf(i67.x, si[6], acci[t]);
            acci[t] = fmaf(i67.y, si[7], acci[t]);
        }
    }
    __syncthreads();
    #pragma unroll
    for (int t = 0; t < 8; t++) {
        sbuf[t*512 + kq*128 + d]        = accr[t];
        sbuf[4096 + t*512 + kq*128 + d] = acci[t];
    }
    __syncthreads();
    #pragma unroll
    for (int j = 0; j < 2; j++) {
        int o = tid + j*512;
        int t = o >> 7, dd = o & 127;
        float vr = (sbuf[t*512 + dd] + sbuf[t*512 + 128 + dd])
                 + (sbuf[t*512 + 256 + dd] + sbuf[t*512 + 384 + dd]);
        float vi = (sbuf[4096 + t*512 + dd] + sbuf[4096 + t*512 + 128 + dd])
                 + (sbuf[4096 + t*512 + 256 + dd] + sbuf[4096 + t*512 + 384 + dd]);
        g_Ar16[(tBase+t)*DHID + dd] = __float2half(vr / (1.0f + expf(-vr)));
        g_Ai16[(tBase+t)*DHID + dd] = __float2half(vi / (1.0f + expf(-vi)));
    }
}

// ---------------- vocab GEMM: fp16 single-pass, A in registers, triple-buffered B ----------------
#define ROWB   272
#define A_MTX  (128*ROWB)
#define B_MTX  (64*ROWB)
#define B_BUF  (2*B_MTX)
#define SMEM_A (2*A_MTX)
#define GEMM_SMEM (SMEM_A + 3*B_BUF)  // 174080
#define TILE_N   64
#define NT_TOT   786
#define CHUNKS   18
#define NT_CHUNK 44

__device__ __forceinline__ void mma_f16(float c[4], const uint32_t a[4], const uint32_t b[2]) {
    asm volatile(
        "mma.sync.aligned.m16n8k16.row.col.f32.f16.f16.f32 "
        "{%0,%1,%2,%3}, {%4,%5,%6,%7}, {%8,%9}, {%0,%1,%2,%3};\n"
        : "+f"(c[0]), "+f"(c[1]), "+f"(c[2]), "+f"(c[3])
        : "r"(a[0]), "r"(a[1]), "r"(a[2]), "r"(a[3]), "r"(b[0]), "r"(b[1]));
}
__device__ __forceinline__ void ldsm_x4(uint32_t r[4], uint32_t addr) {
    asm volatile("ldmatrix.sync.aligned.m8n8.x4.shared.b16 {%0,%1,%2,%3}, [%4];\n"
                 : "=r"(r[0]), "=r"(r[1]), "=r"(r[2]), "=r"(r[3]) : "r"(addr));
}
__device__ __forceinline__ void cp16(uint32_t dst, const void* src, int sz) {
    asm volatile("cp.async.cg.shared.global [%0], [%1], 16, %2;\n"
                 :: "r"(dst), "l"(src), "r"(sz));
}
__device__ __forceinline__ void cp_commit() { asm volatile("cp.async.commit_group;\n"); }
__device__ __forceinline__ void cp_wait1()  { asm volatile("cp.async.wait_group 1;\n"); }
__device__ __forceinline__ float fsqrt_approx(float x) {
    float r; asm("sqrt.approx.f32 %0, %1;" : "=f"(r) : "f"(x)); return r;
}

__device__ __forceinline__ void prefetch_b(uint32_t dstBase, int nBase, int tid) {
    #pragma unroll
    for (int j = 0; j < 8; j++) {
        int idx = tid + j*256;
        int mtx = idx >> 10;
        int rem = idx & 1023;
        int r = rem >> 4, c = rem & 15;
        int v = nBase + r;
        int sz = (v < VOCAB) ? 16 : 0;
        int vc = (v < VOCAB) ? v : (VOCAB-1);
        const __half* s = (mtx == 0) ? g_Wr16 : g_Wi16;
        cp16(dstBase + mtx*B_MTX + r*ROWB + c*16,
             (const char*)(s + (size_t)vc*DHID) + c*16, sz);
    }
}

__global__ void __launch_bounds__(256, 1) gemm_hmma(float* __restrict__ out) {
    extern __shared__ __align__(16) char sm[];
    uint32_t sbase;
    asm("{ .reg .u64 t; cvta.to.shared.u64 t, %1; cvt.u32.u64 %0, t; }" : "=r"(sbase) : "l"(sm));

    const int tid = threadIdx.x;
    const int mBase = blockIdx.y * 128;
    const int ntStart = blockIdx.x * NT_CHUNK;
    int ntEnd = ntStart + NT_CHUNK; if (ntEnd > NT_TOT) ntEnd = NT_TOT;
    const int T = ntEnd - ntStart;
    if (T <= 0) return;

    #pragma unroll
    for (int j = 0; j < 16; j++) {
        int idx = tid + j*256;
        int mtx = idx >> 11;
        int rem = idx & 2047;
        int r = rem >> 4, c = rem & 15;
        const __half* s = (mtx == 0) ? g_Ar16 : g_Ai16;
        cp16(sbase + mtx*A_MTX + r*ROWB + c*16,
             (const char*)(s + (size_t)(mBase + r)*DHID) + c*16, 16);
    }
    prefetch_b(sbase + SMEM_A, ntStart*TILE_N, tid);
    cp_commit();
    prefetch_b(sbase + SMEM_A + B_BUF, (ntStart + 1)*TILE_N, tid);
    cp_commit();

    const int warp = tid >> 5, lane = tid & 31;
    const int wm = warp >> 1, wn = warp & 1;
    const int g = lane >> 2, tg = lane & 3;

    uint32_t aAddr[2][2];
    {
        const int arow = (lane & 7) + (lane & 8);
        const int acol = (lane & 16) ? 16 : 0;
        #pragma unroll
        for (int mtx = 0; mtx < 2; mtx++)
            #pragma unroll
            for (int mf = 0; mf < 2; mf++)
                aAddr[mtx][mf] = sbase + mtx*A_MTX + (wm*32 + mf*16 + arow)*ROWB + acol;
    }
    uint32_t bAddr[2][2];
    {
        const int brow = (lane & 7) + ((lane & 16) ? 8 : 0);
        const int bcol = (lane & 8) ? 16 : 0;
        #pragma unroll
        for (int mtx = 0; mtx < 2; mtx++)
            #pragma unroll
            for (int p = 0; p < 2; p++)
                bAddr[mtx][p] = sbase + SMEM_A + mtx*B_MTX + (wn*32 + p*16 + brow)*ROWB + bcol;
    }

    uint32_t Ar[2][8][4], Ai[2][8][4];

    for (int t = 0; t < T; t++) {
        cp_wait1();
        __syncthreads();

        if (t == 0) {
            #pragma unroll
            for (int mf = 0; mf < 2; mf++)
                #pragma unroll
                for (int ks = 0; ks < 8; ks++) {
                    ldsm_x4(Ar[mf][ks], aAddr[0][mf] + ks*32);
                    ldsm_x4(Ai[mf][ks], aAddr[1][mf] + ks*32);
                }
        }

        prefetch_b(sbase + SMEM_A + ((t + 2) % 3)*B_BUF, (ntStart + t + 2)*TILE_N, tid);
        cp_commit();

        const uint32_t bufOff = (uint32_t)(t % 3)*B_BUF;

        float acc[2][2][4][4];
        #pragma unroll
        for (int o = 0; o < 2; o++)
            #pragma unroll
            for (int mf = 0; mf < 2; mf++)
                #pragma unroll
                for (int nf = 0; nf < 4; nf++)
                    #pragma unroll
                    for (int q = 0; q < 4; q++) acc[o][mf][nf][q] = 0.f;

        #pragma unroll
        for (int ks = 0; ks < 8; ks++) {
            const uint32_t kb = ks*32;
            uint32_t Wr[2][4], Wi[2][4];
            #pragma unroll
            for (int p = 0; p < 2; p++) {
                ldsm_x4(Wr[p], bAddr[0][p] + bufOff + kb);
                ldsm_x4(Wi[p], bAddr[1][p] + bufOff + kb);
            }
            #pragma unroll
            for (int mf = 0; mf < 2; mf++)
                #pragma unroll
                for (int nf = 0; nf < 4; nf++)
                    mma_f16(acc[0][mf][nf], Ar[mf][ks], &Wr[nf>>1][(nf&1)*2]);
            #pragma unroll
            for (int mf = 0; mf < 2; mf++)
                #pragma unroll
                for (int nf = 0; nf < 4; nf++)
                    mma_f16(acc[1][mf][nf], Ai[mf][ks], &Wr[nf>>1][(nf&1)*2]);
            #pragma unroll
            for (int mf = 0; mf < 2; mf++)
                #pragma unroll
                for (int nf = 0; nf < 4; nf++)
                    mma_f16(acc[1][mf][nf], Ar[mf][ks], &Wi[nf>>1][(nf&1)*2]);
            #pragma unroll
            for (int mf = 0; mf < 2; mf++) {
                uint32_t An[4];
                #pragma unroll
                for (int q = 0; q < 4; q++) An[q] = Ai[mf][ks][q] ^ 0x80008000u;
                #pragma unroll
                for (int nf = 0; nf < 4; nf++)
                    mma_f16(acc[0][mf][nf], An, &Wi[nf>>1][(nf&1)*2]);
            }
        }

        // epilogue (scalar stores: VOCAB odd -> only 4B alignment guaranteed)
        const int nBase = (ntStart + t)*TILE_N;
        #pragma unroll
        for (int mf = 0; mf < 2; mf++) {
            const int row = mBase + wm*32 + mf*16 + g;
            #pragma unroll
            for (int nf = 0; nf < 4; nf++) {
                const int col = nBase + wn*32 + nf*8 + 2*tg;
                float* o0 = out + (size_t)row*VOCAB + col;
                float* o1 = o0 + (size_t)8*VOCAB;
                float lr0 = acc[0][mf][nf][0], li0 = acc[1][mf][nf][0];
                float lr1 = acc[0][mf][nf][1], li1 = acc[1][mf][nf][1];
                float lr2 = acc[0][mf][nf][2], li2 = acc[1][mf][nf][2];
                float lr3 = acc[0][mf][nf][3], li3 = acc[1][mf][nf][3];
                if (col < VOCAB) {
                    o0[0] = fsqrt_approx(fmaf(lr0,lr0,fmaf(li0,li0,1e-8f)));
                    o1[0] = fsqrt_approx(fmaf(lr2,lr2,fmaf(li2,li2,1e-8f)));
                }
                if (col + 1 < VOCAB) {
                    o0[1] = fsqrt_approx(fmaf(lr1,lr1,fmaf(li1,li1,1e-8f)));
                    o1[1] = fsqrt_approx(fmaf(lr3,lr3,fmaf(li3,li3,1e-8f)));
                }
            }
        }
    }
}

// ---------------- launch ----------------
extern "C" void kernel_launch(void* const* d_in, const int* in_sizes, int n_in,
                              void* d_out, int out_size) {
    const int*   ids  = (const int*)  d_in[0];
    const float* emb  = (const float*)d_in[1];
    const float* cw   = (const float*)d_in[2];
    const float* cb   = (const float*)d_in[3];
    const float* W    = (const float*)d_in[4];
    const float* Bp   = (const float*)d_in[5];
    const float* acos_= (const float*)d_in[6];
    const float* asin_= (const float*)d_in[7];
    const float* opr  = (const float*)d_in[8];
    const float* opi  = (const float*)d_in[9];
    const float* Wr   = (const float*)d_in[10];
    const float* Wi   = (const float*)d_in[11];
    float* out = (float*)d_out;

    cudaFuncSetAttribute(gemm_hmma, cudaFuncAttributeMaxDynamicSharedMemorySize, GEMM_SMEM);

    wsplit_kernel<<<(VOCAB*DHID + 255)/256, 256>>>(Wr, Wi);
    opsplit_kernel<<<(DHID*NFREQ)/256, 256>>>(opr + (size_t)DHID*NFREQ,
                                              opi + (size_t)DHID*NFREQ);

    for (int l = 0; l < 2; l++) {
        xc_kernel<<<NTOK/8, 512>>>(cw + (size_t)l*DHID*2*DHID, cb + (size_t)l*DHID,
                                   ids, emb, (l == 0) ? 1 : 0);
        dim3 tg(NFREQ/4, NTOK/32);
        theta_kernel<<<tg, 128>>>(W + (size_t)l*NFREQ*DHID, Bp + (size_t)l*NFREQ*DHID,
                                  acos_ + (size_t)l*NFREQ*DHID, asin_ + (size_t)l*NFREQ*DHID);
        if (l == 0) {
            op_kernel<<<NTOK/8, 512>>>(opr, opi);
        } else {
            op16_kernel<<<NTOK/8, 512>>>();
        }
    }

    gemm_hmma<<<dim3(CHUNKS, 8), 256, GEMM_SMEM>>>(out);
}

// round 17
// speedup vs baseline: 1.5227x; 1.5227x over previous
#include <cuda_runtime.h>
#include <cuda_fp16.h>
#include <math.h>
#include <stdint.h>

#define VOCAB 50257
#define DHID  128
#define NTOK  1024
#define NFREQ 256
#define SEQ   512

// ---------------- device scratch ----------------
__device__ __align__(16) float g_xr[NTOK*DHID];
__device__ __align__(16) float g_xi[NTOK*DHID];
__device__ __align__(16) float g_xc[NTOK*DHID];
__device__ __align__(16) float g_cs[NTOK*NFREQ];
__device__ __align__(16) float g_ss[NTOK*NFREQ];
__device__ __align__(16) __half g_Wr16[VOCAB*DHID];
__device__ __align__(16) __half g_Wi16[VOCAB*DHID];
__device__ __align__(16) __half g_Ar16[NTOK*DHID];
__device__ __align__(16) __half g_Ai16[NTOK*DHID];
__device__ __align__(16) __half g_opr16[DHID*NFREQ];   // layer-1 op weights only
__device__ __align__(16) __half g_opi16[DHID*NFREQ];

// ---------------- small kernels ----------------
__global__ void wsplit_kernel(const float* __restrict__ Wr, const float* __restrict__ Wi) {
    int i = blockIdx.x*256 + threadIdx.x;
    if (i < VOCAB*DHID) {
        g_Wr16[i] = __float2half(Wr[i]);
        g_Wi16[i] = __float2half(Wi[i]);
    }
}

__global__ void opsplit_kernel(const float* __restrict__ opr1, const float* __restrict__ opi1) {
    int i = blockIdx.x*256 + threadIdx.x;   // 128*256 = 32768 elements (layer 1)
    g_opr16[i] = __float2half(opr1[i]);
    g_opi16[i] = __float2half(opi1[i]);
}

// xc[t][d] = sum_k in[t][k] * cw[d][k] + cb[d]   (K=256, fp32 weights — LUT-sensitive)
// 8 tokens/block, 512 threads, split-K x4, grid 128 (proven R13 config).
__global__ void __launch_bounds__(512, 2)
xc_kernel(const float* __restrict__ cwl, const float* __restrict__ cbl,
          const int* __restrict__ ids, const float* __restrict__ emb,
          int gather) {
    __shared__ __align__(16) float sbuf[4096];   // inputs 8KB -> partials 16KB
    float* xs = sbuf;                            // [8][256]
    int tid = threadIdx.x, tBase = blockIdx.x*8;
    if (gather) {
        for (int i = tid; i < 8*256; i += 512) {
            int t = i >> 8, k = i & 255;
            xs[i] = emb[(size_t)ids[tBase+t]*256 + k];
        }
    } else {
        for (int i = tid; i < 8*256; i += 512) {
            int t = i >> 8, k = i & 255;
            xs[i] = (k < 128) ? g_xr[(tBase+t)*DHID + k] : g_xi[(tBase+t)*DHID + k - 128];
        }
    }
    __syncthreads();
    const int d = tid & 127, kq = tid >> 7;
    const int k0 = kq*64;
    float acc[8];
    #pragma unroll
    for (int t = 0; t < 8; t++) acc[t] = 0.f;
    #pragma unroll 4
    for (int k = k0; k < k0 + 64; k += 4) {
        float4 w = *reinterpret_cast<const float4*>(&cwl[d*256 + k]);
        #pragma unroll
        for (int t = 0; t < 8; t++) {
            acc[t] = fmaf(w.x, xs[t*256+k+0], acc[t]);
            acc[t] = fmaf(w.y, xs[t*256+k+1], acc[t]);
            acc[t] = fmaf(w.z, xs[t*256+k+2], acc[t]);
            acc[t] = fmaf(w.w, xs[t*256+k+3], acc[t]);
        }
    }
    __syncthreads();
    #pragma unroll
    for (int t = 0; t < 8; t++) sbuf[t*512 + kq*128 + d] = acc[t];
    __syncthreads();
    #pragma unroll
    for (int j = 0; j < 2; j++) {
        int o = tid + j*512;
        int t = o >> 7, dd = o & 127;
        float v = (sbuf[t*512 + dd] + sbuf[t*512 + 128 + dd])
                + (sbuf[t*512 + 256 + dd] + sbuf[t*512 + 384 + dd]);
        g_xc[(tBase+t)*DHID + dd] = v + cbl[dd];
    }
}

// lane = token, warp = frequency: serial d-accumulation, no shuffles.
__global__ void theta_kernel(const float* __restrict__ Wl, const float* __restrict__ Bpl,
                             const float* __restrict__ acl, const float* __restrict__ asl) {
    __shared__ __align__(16) float  xs[32*129];
    __shared__ __align__(16) float4 wt[4*128];
    const float KSCALE = (float)(4096.0 / 6.283185307179586);
    const float ASTEP  = (float)(6.283185307179586 / 4096.0);
    const float PHI_F  = 1.6180339887498948f;
    const int tid = threadIdx.x, warp = tid >> 5, lane = tid & 31;
    const int nBase = blockIdx.x*4;
    const int tBase = blockIdx.y*32;

    for (int i = tid; i < 32*128; i += 128) {
        int t = i >> 7, d = i & 127;
        xs[t*129 + d] = g_xc[(tBase+t)*DHID + d];
    }
    for (int i = tid; i < 4*128; i += 128) {
        int n = nBase + (i >> 7), d = i & 127;
        float w = Wl[n*DHID + d];
        wt[i] = make_float4(1.0f/(1.0f + fabsf(w)), Bpl[n*DHID + d],
                            acl[n*DHID + d], asl[n*DHID + d]);
    }
    __syncthreads();

    const int n = nBase + warp;
    const int tok = tBase + lane;
    const float tpos = (float)(tok & (SEQ-1)) * PHI_F;
    const float4* wrow = wt + warp*128;
    const float*  xrow = xs + lane*129;
    float cs = 0.f, ss = 0.f;
    #pragma unroll 4
    for (int d = 0; d < 128; d++) {
        float4 c = wrow[d];
        float th = fmaf(xrow[d], c.x, c.y) + tpos;
        int idx = __float2int_rd(th * KSCALE) & 4095;
        float sv, cv;
        __sincosf((float)idx * ASTEP, &sv, &cv);
        cs = fmaf(cv, c.z, cs);
        ss = fmaf(sv, c.w, ss);
    }
    g_cs[tok*NFREQ + n] = cs;
    g_ss[tok*NFREQ + n] = ss;
}

// Layer 0: xr/xi = silu(cs @ opr^T), silu(ss @ opi^T)  — fp32 weights (bit-exact R13 path)
__global__ void __launch_bounds__(512, 2)
op_kernel(const float* __restrict__ oprl, const float* __restrict__ opil) {
    __shared__ __align__(16) float sbuf[8192];
    float* cs_s = sbuf;          // [8][256]
    float* ss_s = sbuf + 2048;   // [8][256]
    int tid = threadIdx.x, tBase = blockIdx.x*8;
    for (int i = tid; i < 8*256; i += 512) {
        int t = i >> 8, k = i & 255;
        cs_s[i] = g_cs[(tBase+t)*NFREQ + k];
        ss_s[i] = g_ss[(tBase+t)*NFREQ + k];
    }
    __syncthreads();
    const int d = tid & 127, kq = tid >> 7;
    const int k0 = kq*64;
    float accr[8], acci[8];
    #pragma unroll
    for (int t = 0; t < 8; t++) { accr[t] = 0.f; acci[t] = 0.f; }
    #pragma unroll 2
    for (int k = k0; k < k0 + 64; k += 4) {
        float4 wr = *reinterpret_cast<const float4*>(&oprl[d*256 + k]);
        float4 wi = *reinterpret_cast<const float4*>(&opil[d*256 + k]);
        #pragma unroll
        for (int t = 0; t < 8; t++) {
            accr[t] = fmaf(wr.x, cs_s[t*256+k+0], accr[t]);
            accr[t] = fmaf(wr.y, cs_s[t*256+k+1], accr[t]);
            accr[t] = fmaf(wr.z, cs_s[t*256+k+2], accr[t]);
            accr[t] = fmaf(wr.w, cs_s[t*256+k+3], accr[t]);
            acci[t] = fmaf(wi.x, ss_s[t*256+k+0], acci[t]);
            acci[t] = fmaf(wi.y, ss_s[t*256+k+1], acci[t]);
            acci[t] = fmaf(wi.z, ss_s[t*256+k+2], acci[t]);
            acci[t] = fmaf(wi.w, ss_s[t*256+k+3], acci[t]);
        }
    }
    __syncthreads();
    #pragma unroll
    for (int t = 0; t < 8; t++) {
        sbuf[t*512 + kq*128 + d]        = accr[t];
        sbuf[4096 + t*512 + kq*128 + d] = acci[t];
    }
    __syncthreads();
    #pragma unroll
    for (int j = 0; j < 2; j++) {
        int o = tid + j*512;
        int t = o >> 7, dd = o & 127;
        float vr = (sbuf[t*512 + dd] + sbuf[t*512 + 128 + dd])
                 + (sbuf[t*512 + 256 + dd] + sbuf[t*512 + 384 + dd]);
        float vi = (sbuf[4096 + t*512 + dd] + sbuf[4096 + t*512 + 128 + dd])
                 + (sbuf[4096 + t*512 + 256 + dd] + sbuf[4096 + t*512 + 384 + dd]);
        g_xr[(tBase+t)*DHID + dd] = vr / (1.0f + expf(-vr));
        g_xi[(tBase+t)*DHID + dd] = vi / (1.0f + expf(-vi));
    }
}

// Layer 1: same GEMM but fp16 weights (output only feeds the fp16 final GEMM);
// writes fp16 A operands directly.
__global__ void __launch_bounds__(512, 2)
op16_kernel() {
    __shared__ __align__(16) float sbuf[8192];
    float* cs_s = sbuf;          // [8][256]
    float* ss_s = sbuf + 2048;   // [8][256]
    int tid = threadIdx.x, tBase = blockIdx.x*8;
    for (int i = tid; i < 8*256; i += 512) {
        int t = i >> 8, k = i & 255;
        cs_s[i] = g_cs[(tBase+t)*NFREQ + k];
        ss_s[i] = g_ss[(tBase+t)*NFREQ + k];
    }
    __syncthreads();
    const int d = tid & 127, kq = tid >> 7;
    const int k0 = kq*64;
    const __half* wr16 = g_opr16 + d*256;
    const __half* wi16 = g_opi16 + d*256;
    float accr[8], acci[8];
    #pragma unroll
    for (int t = 0; t < 8; t++) { accr[t] = 0.f; acci[t] = 0.f; }
    #pragma unroll 2
    for (int k = k0; k < k0 + 64; k += 8) {
        uint4 rv = *reinterpret_cast<const uint4*>(wr16 + k);
        uint4 iv = *reinterpret_cast<const uint4*>(wi16 + k);
        float2 r01 = __half22float2(*reinterpret_cast<__half2*>(&rv.x));
        float2 r23 = __half22float2(*reinterpret_cast<__half2*>(&rv.y));
        float2 r45 = __half22float2(*reinterpret_cast<__half2*>(&rv.z));
        float2 r67 = __half22float2(*reinterpret_cast<__half2*>(&rv.w));
        float2 i01 = __half22float2(*reinterpret_cast<__half2*>(&iv.x));
        float2 i23 = __half22float2(*reinterpret_cast<__half2*>(&iv.y));
        float2 i45 = __half22float2(*reinterpret_cast<__half2*>(&iv.z));
        float2 i67 = __half22float2(*reinterpret_cast<__half2*>(&iv.w));
        #pragma unroll
        for (int t = 0; t < 8; t++) {
            const float* cr = cs_s + t*256 + k;
            const float* si = ss_s + t*256 + k;
            accr[t] = fmaf(r01.x, cr[0], accr[t]);
            accr[t] = fmaf(r01.y, cr[1], accr[t]);
            accr[t] = fmaf(r23.x, cr[2], accr[t]);
            accr[t] = fmaf(r23.y, cr[3], accr[t]);
            accr[t] = fmaf(r45.x, cr[4], accr[t]);
            accr[t] = fmaf(r45.y, cr[5], accr[t]);
            accr[t] = fmaf(r67.x, cr[6], accr[t]);
            accr[t] = fmaf(r67.y, cr[7], accr[t]);
            acci[t] = fmaf(i01.x, si[0], acci[t]);
            acci[t] = fmaf(i01.y, si[1], acci[t]);
            acci[t] = fmaf(i23.x, si[2], acci[t]);
            acci[t] = fmaf(i23.y, si[3], acci[t]);
            acci[t] = fmaf(i45.x, si[4], acci[t]);
            acci[t] = fmaf(i45.y, si[5], acci[t]);
            acci[t] = fmaf(i67.x, si[6], acci[t]);
            acci[t] = fmaf(i67.y, si[7], acci[t]);
        }
    }
    __syncthreads();
    #pragma unroll
    for (int t = 0; t < 8; t++) {
        sbuf[t*512 + kq*128 + d]        = accr[t];
        sbuf[4096 + t*512 + kq*128 + d] = acci[t];
    }
    __syncthreads();
    #pragma unroll
    for (int j = 0; j < 2; j++) {
        int o = tid + j*512;
        int t = o >> 7, dd = o & 127;
        float vr = (sbuf[t*512 + dd] + sbuf[t*512 + 128 + dd])
                 + (sbuf[t*512 + 256 + dd] + sbuf[t*512 + 384 + dd]);
        float vi = (sbuf[4096 + t*512 + dd] + sbuf[4096 + t*512 + 128 + dd])
                 + (sbuf[4096 + t*512 + 256 + dd] + sbuf[4096 + t*512 + 384 + dd]);
        g_Ar16[(tBase+t)*DHID + dd] = __float2half(vr / (1.0f + expf(-vr)));
        g_Ai16[(tBase+t)*DHID + dd] = __float2half(vi / (1.0f + expf(-vi)));
    }
}

// ---------------- vocab GEMM: fp16 single-pass, A in registers, triple-buffered B ----------------
#define ROWB   272
#define A_MTX  (128*ROWB)
#define B_MTX  (64*ROWB)
#define B_BUF  (2*B_MTX)
#define SMEM_A (2*A_MTX)
#define GEMM_SMEM (SMEM_A + 3*B_BUF)  // 174080
#define TILE_N   64
#define NT_TOT   786
#define CHUNKS   18
#define NT_CHUNK 44

__device__ __forceinline__ void mma_f16(float c[4], const uint32_t a[4], const uint32_t b[2]) {
    asm volatile(
        "mma.sync.aligned.m16n8k16.row.col.f32.f16.f16.f32 "
        "{%0,%1,%2,%3}, {%4,%5,%6,%7}, {%8,%9}, {%0,%1,%2,%3};\n"
        : "+f"(c[0]), "+f"(c[1]), "+f"(c[2]), "+f"(c[3])
        : "r"(a[0]), "r"(a[1]), "r"(a[2]), "r"(a[3]), "r"(b[0]), "r"(b[1]));
}
__device__ __forceinline__ void ldsm_x4(uint32_t r[4], uint32_t addr) {
    asm volatile("ldmatrix.sync.aligned.m8n8.x4.shared.b16 {%0,%1,%2,%3}, [%4];\n"
                 : "=r"(r[0]), "=r"(r[1]), "=r"(r[2]), "=r"(r[3]) : "r"(addr));
}
__device__ __forceinline__ void cp16(uint32_t dst, const void* src, int sz) {
    asm volatile("cp.async.cg.shared.global [%0], [%1], 16, %2;\n"
                 :: "r"(dst), "l"(src), "r"(sz));
}
__device__ __forceinline__ void cp_commit() { asm volatile("cp.async.commit_group;\n"); }
__device__ __forceinline__ void cp_wait1()  { asm volatile("cp.async.wait_group 1;\n"); }
__device__ __forceinline__ float fsqrt_approx(float x) {
    float r; asm("sqrt.approx.f32 %0, %1;" : "=f"(r) : "f"(x)); return r;
}

__device__ __forceinline__ void prefetch_b(uint32_t dstBase, int nBase, int tid) {
    #pragma unroll
    for (int j = 0; j < 8; j++) {
        int idx = tid + j*256;
        int mtx = idx >> 10;
        int rem = idx & 1023;
        int r = rem >> 4, c = rem & 15;
        int v = nBase + r;
        int sz = (v < VOCAB) ? 16 : 0;
        int vc = (v < VOCAB) ? v : (VOCAB-1);
        const __half* s = (mtx == 0) ? g_Wr16 : g_Wi16;
        cp16(dstBase + mtx*B_MTX + r*ROWB + c*16,
             (const char*)(s + (size_t)vc*DHID) + c*16, sz);
    }
}

__global__ void __launch_bounds__(256, 1) gemm_hmma(float* __restrict__ out) {
    extern __shared__ __align__(16) char sm[];
    uint32_t sbase;
    asm("{ .reg .u64 t; cvta.to.shared.u64 t, %1; cvt.u32.u64 %0, t; }" : "=r"(sbase) : "l"(sm));

    const int tid = threadIdx.x;
    const int mBase = blockIdx.y * 128;
    const int ntStart = blockIdx.x * NT_CHUNK;
    int ntEnd = ntStart + NT_CHUNK; if (ntEnd > NT_TOT) ntEnd = NT_TOT;
    const int T = ntEnd - ntStart;
    if (T <= 0) return;

    #pragma unroll
    for (int j = 0; j < 16; j++) {
        int idx = tid + j*256;
        int mtx = idx >> 11;
        int rem = idx & 2047;
        int r = rem >> 4, c = rem & 15;
        const __half* s = (mtx == 0) ? g_Ar16 : g_Ai16;
        cp16(sbase + mtx*A_MTX + r*ROWB + c*16,
             (const char*)(s + (size_t)(mBase + r)*DHID) + c*16, 16);
    }
    prefetch_b(sbase + SMEM_A, ntStart*TILE_N, tid);
    cp_commit();
    prefetch_b(sbase + SMEM_A + B_BUF, (ntStart + 1)*TILE_N, tid);
    cp_commit();

    const int warp = tid >> 5, lane = tid & 31;
    const int wm = warp >> 1, wn = warp & 1;
    const int g = lane >> 2, tg = lane & 3;

    uint32_t aAddr[2][2];
    {
        const int arow = (lane & 7) + (lane & 8);
        const int acol = (lane & 16) ? 16 : 0;
        #pragma unroll
        for (int mtx = 0; mtx < 2; mtx++)
            #pragma unroll
            for (int mf = 0; mf < 2; mf++)
                aAddr[mtx][mf] = sbase + mtx*A_MTX + (wm*32 + mf*16 + arow)*ROWB + acol;
    }
    uint32_t bAddr[2][2];
    {
        const int brow = (lane & 7) + ((lane & 16) ? 8 : 0);
        const int bcol = (lane & 8) ? 16 : 0;
        #pragma unroll
        for (int mtx = 0; mtx < 2; mtx++)
            #pragma unroll
            for (int p = 0; p < 2; p++)
                bAddr[mtx][p] = sbase + SMEM_A + mtx*B_MTX + (wn*32 + p*16 + brow)*ROWB + bcol;
    }

    uint32_t Ar[2][8][4], Ai[2][8][4];

    for (int t = 0; t < T; t++) {
        cp_wait1();
        __syncthreads();

        if (t == 0) {
            #pragma unroll
            for (int mf = 0; mf < 2; mf++)
                #pragma unroll
                for (int ks = 0; ks < 8; ks++) {
                    ldsm_x4(Ar[mf][ks], aAddr[0][mf] + ks*32);
                    ldsm_x4(Ai[mf][ks], aAddr[1][mf] + ks*32);
                }
        }

        prefetch_b(sbase + SMEM_A + ((t + 2) % 3)*B_BUF, (ntStart + t + 2)*TILE_N, tid);
        cp_commit();

        const uint32_t bufOff = (uint32_t)(t % 3)*B_BUF;

        float acc[2][2][4][4];
        #pragma unroll
        for (int o = 0; o < 2; o++)
            #pragma unroll
            for (int mf = 0; mf < 2; mf++)
                #pragma unroll
                for (int nf = 0; nf < 4; nf++)
                    #pragma unroll
                    for (int q = 0; q < 4; q++) acc[o][mf][nf][q] = 0.f;

        #pragma unroll
        for (int ks = 0; ks < 8; ks++) {
            const uint32_t kb = ks*32;
            uint32_t Wr[2][4], Wi[2][4];
            #pragma unroll
            for (int p = 0; p < 2; p++) {
                ldsm_x4(Wr[p], bAddr[0][p] + bufOff + kb);
                ldsm_x4(Wi[p], bAddr[1][p] + bufOff + kb);
            }
            #pragma unroll
            for (int mf = 0; mf < 2; mf++)
                #pragma unroll
                for (int nf = 0; nf < 4; nf++)
                    mma_f16(acc[0][mf][nf], Ar[mf][ks], &Wr[nf>>1][(nf&1)*2]);
            #pragma unroll
            for (int mf = 0; mf < 2; mf++)
                #pragma unroll
                for (int nf = 0; nf < 4; nf++)
                    mma_f16(acc[1][mf][nf], Ai[mf][ks], &Wr[nf>>1][(nf&1)*2]);
            #pragma unroll
            for (int mf = 0; mf < 2; mf++)
                #pragma unroll
                for (int nf = 0; nf < 4; nf++)
                    mma_f16(acc[1][mf][nf], Ar[mf][ks], &Wi[nf>>1][(nf&1)*2]);
            #pragma unroll
            for (int mf = 0; mf < 2; mf++) {
                uint32_t An[4];
                #pragma unroll
                for (int q = 0; q < 4; q++) An[q] = Ai[mf][ks][q] ^ 0x80008000u;
                #pragma unroll
                for (int nf = 0; nf < 4; nf++)
                    mma_f16(acc[0][mf][nf], An, &Wi[nf>>1][(nf&1)*2]);
            }
        }

        // epilogue (scalar stores: VOCAB odd -> only 4B alignment guaranteed)
        const int nBase = (ntStart + t)*TILE_N;
        #pragma unroll
        for (int mf = 0; mf < 2; mf++) {
            const int row = mBase + wm*32 + mf*16 + g;
            #pragma unroll
            for (int nf = 0; nf < 4; nf++) {
                const int col = nBase + wn*32 + nf*8 + 2*tg;
                float* o0 = out + (size_t)row*VOCAB + col;
                float* o1 = o0 + (size_t)8*VOCAB;
                float lr0 = acc[0][mf][nf][0], li0 = acc[1][mf][nf][0];
                float lr1 = acc[0][mf][nf][1], li1 = acc[1][mf][nf][1];
                float lr2 = acc[0][mf][nf][2], li2 = acc[1][mf][nf][2];
                float lr3 = acc[0][mf][nf][3], li3 = acc[1][mf][nf][3];
                if (col < VOCAB) {
                    o0[0] = fsqrt_approx(fmaf(lr0,lr0,fmaf(li0,li0,1e-8f)));
                    o1[0] = fsqrt_approx(fmaf(lr2,lr2,fmaf(li2,li2,1e-8f)));
                }
                if (col + 1 < VOCAB) {
                    o0[1] = fsqrt_approx(fmaf(lr1,lr1,fmaf(li1,li1,1e-8f)));
                    o1[1] = fsqrt_approx(fmaf(lr3,lr3,fmaf(li3,li3,1e-8f)));
                }
            }
        }
    }
}

// ---------------- launch ----------------
extern "C" void kernel_launch(void* const* d_in, const int* in_sizes, int n_in,
                              void* d_out, int out_size) {
    const int*   ids  = (const int*)  d_in[0];
    const float* emb  = (const float*)d_in[1];
    const float* cw   = (const float*)d_in[2];
    const float* cb   = (const float*)d_in[3];
    const float* W    = (const float*)d_in[4];
    const float* Bp   = (const float*)d_in[5];
    const float* acos_= (const float*)d_in[6];
    const float* asin_= (const float*)d_in[7];
    const float* opr  = (const float*)d_in[8];
    const float* opi  = (const float*)d_in[9];
    const float* Wr   = (const float*)d_in[10];
    const float* Wi   = (const float*)d_in[11];
    float* out = (float*)d_out;

    cudaFuncSetAttribute(gemm_hmma, cudaFuncAttributeMaxDynamicSharedMemorySize, GEMM_SMEM);

    wsplit_kernel<<<(VOCAB*DHID + 255)/256, 256>>>(Wr, Wi);
    opsplit_kernel<<<(DHID*NFREQ)/256, 256>>>(opr + (size_t)DHID*NFREQ,
                                              opi + (size_t)DHID*NFREQ);

    for (int l = 0; l < 2; l++) {
        xc_kernel<<<NTOK/8, 512>>>(cw + (size_t)l*DHID*2*DHID, cb + (size_t)l*DHID,
                                   ids, emb, (l == 0) ? 1 : 0);
        dim3 tg(NFREQ/4, NTOK/32);
        theta_kernel<<<tg, 128>>>(W + (size_t)l*NFREQ*DHID, Bp + (size_t)l*NFREQ*DHID,
                                  acos_ + (size_t)l*NFREQ*DHID, asin_ + (size_t)l*NFREQ*DHID);
        if (l == 0) {
            op_kernel<<<NTOK/8, 512>>>(opr, opi);
        } else {
            op16_kernel<<<NTOK/8, 512>>>();
        }
    }

    gemm_hmma<<<dim3(CHUNKS, 8), 256, GEMM_SMEM>>>(out);
}